// round 4
// baseline (speedup 1.0000x reference)
#include <cuda_runtime.h>

#define NN 50000
#define EE 600000
#define FF 128
#define RR 4
#define RN (RR * NN)               // 200000 segments
#define NBLK ((RN + 1023) / 1024)  // 196 scan blocks

// ---------------- scratch (static device globals; no allocation) ----------------
__device__ __align__(16) float g_agg[(size_t)RR * NN * FF];   // x + sum of neighbors
__device__ __align__(16) float g_h[(size_t)RR * NN * FF];     // output of first linear
__device__ float g_sum[RR * FF];
__device__ float g_sumsq[RR * FF];
__device__ float g_scale[RR * FF];
__device__ float g_shift[RR * FF];
__device__ int g_cnt[RN];     // per-segment edge count
__device__ int g_off[RN];     // intra-block exclusive scan of counts
__device__ int g_bsum[256];   // per-scan-block totals
__device__ int g_bscan[256];  // exclusive scan of block totals
__device__ int g_cur[RN];     // reorder cursors
__device__ int g_srcbuf[EE];  // edge sources sorted by segment

typedef unsigned long long ull;

__device__ __forceinline__ ull pack2(float lo, float hi) {
    ull r;
    asm("mov.b64 %0, {%1,%2};" : "=l"(r) : "f"(lo), "f"(hi));
    return r;
}
__device__ __forceinline__ void unpack2(ull v, float& lo, float& hi) {
    asm("mov.b64 {%0,%1}, %2;" : "=f"(lo), "=f"(hi) : "l"(v));
}
__device__ __forceinline__ void dfma(ull& d, ull a, ull b) {
    asm("fma.rn.f32x2 %0, %1, %2, %0;" : "+l"(d) : "l"(a), "l"(b));
}

// ---------------- histogram of segment ids (+ zero BN stats) --------------------
__global__ void hist_kernel(const int* __restrict__ ei, const int* __restrict__ et) {
    int e = blockIdx.x * blockDim.x + threadIdx.x;
    if (blockIdx.x == 0) {
        for (int i = threadIdx.x; i < RR * FF; i += blockDim.x) {
            g_sum[i] = 0.f;
            g_sumsq[i] = 0.f;
        }
    }
    if (e < EE) {
        int s = et[e] * NN + ei[e];
        atomicAdd(&g_cnt[s], 1);
    }
}

// ---------------- scan stage 1: per-1024-block exclusive scan (+ zero g_cur) ----
__global__ void scan1_kernel() {
    __shared__ int sh[512];
    int t = threadIdx.x;
    int base = blockIdx.x * 1024;
    int i0 = base + 2 * t, i1 = i0 + 1;
    int c0 = (i0 < RN) ? g_cnt[i0] : 0;
    int c1 = (i1 < RN) ? g_cnt[i1] : 0;
    if (i0 < RN) g_cur[i0] = 0;
    if (i1 < RN) g_cur[i1] = 0;
    int s = c0 + c1;
    sh[t] = s;
    __syncthreads();
    for (int d = 1; d < 512; d <<= 1) {
        int v = (t >= d) ? sh[t - d] : 0;
        __syncthreads();
        sh[t] += v;
        __syncthreads();
    }
    int excl = sh[t] - s;
    if (i0 < RN) g_off[i0] = excl;
    if (i1 < RN) g_off[i1] = excl + c0;
    if (t == 511) g_bsum[blockIdx.x] = sh[511];
}

// ---------------- scan stage 2: scan the 196 block totals -----------------------
__global__ void scan2_kernel() {
    __shared__ int sh[256];
    int t = threadIdx.x;
    int v = (t < NBLK) ? g_bsum[t] : 0;
    sh[t] = v;
    __syncthreads();
    for (int d = 1; d < 256; d <<= 1) {
        int u = (t >= d) ? sh[t - d] : 0;
        __syncthreads();
        sh[t] += u;
        __syncthreads();
    }
    g_bscan[t] = sh[t] - v;
}

// ---------------- reorder edges into segment-sorted order -----------------------
__global__ void reorder_kernel(const int* __restrict__ ei, const int* __restrict__ et) {
    int e = blockIdx.x * blockDim.x + threadIdx.x;
    if (e >= EE) return;
    int s = et[e] * NN + ei[e];
    int base = g_off[s] + g_bscan[s >> 10];
    int pos = base + atomicAdd(&g_cur[s], 1);
    g_srcbuf[pos] = ei[EE + e];
}

// ---------------- segmented sum: g_agg[seg] = x[row] + sum x[src] ----------------
__global__ void segsum_kernel(const float4* __restrict__ x4) {
    int warp = (blockIdx.x * blockDim.x + threadIdx.x) >> 5;
    int lane = threadIdx.x & 31;
    if (warp >= RN) return;
    int row = warp % NN;
    int start = g_off[warp] + g_bscan[warp >> 10];
    int cnt = g_cnt[warp];
    float4 acc = x4[(size_t)row * 32 + lane];
    for (int i = 0; i < cnt; ++i) {
        int src = g_srcbuf[start + i];
        float4 v = x4[(size_t)src * 32 + lane];
        acc.x += v.x; acc.y += v.y; acc.z += v.z; acc.w += v.w;
    }
    ((float4*)g_agg)[(size_t)warp * 32 + lane] = acc;
}

// ----- smem tile loaders: A duplicated (a,a) pairs; W paired (c, c+16) ----------
// Asd: [row][k] float2 = (A[row][k], A[row][k])           (32768 floats, 128 KB)
// Wsp: [k][p]   float2 = (W[k][32*(p/16)+(p%16)], +16)    (16384 floats,  64 KB)
__device__ __forceinline__ void load_w_paired(float* Wsp, const float4* W4, int tid) {
#pragma unroll
    for (int it = 0; it < 16; ++it) {
        int q = it * 256 + tid;        // 4096 float4 = 128x128 W
        float4 v = W4[q];
        int k = q >> 5;
        int u0 = (q & 31) * 4;
        int jj = u0 >> 5, h = (u0 >> 4) & 1, txp = u0 & 15;
        float* dst = Wsp + (size_t)(k * 64 + jj * 16 + txp) * 2 + h;
        dst[0] = v.x; dst[2] = v.y; dst[4] = v.z; dst[6] = v.w;
    }
}

// ---------------- GEMM1: g_h[r] = g_agg[r] @ W1[r] + b1[r], fused BN stats -------
__global__ __launch_bounds__(256) void gemm1_kernel(const float* __restrict__ W1g,
                                                    const float* __restrict__ b1g) {
    extern __shared__ float sh[];
    float* Asd = sh;            // 32768 floats
    float* Wsp = sh + 32768;    // 16384 floats
    const int r = blockIdx.y;
    const int row0 = blockIdx.x * 128;
    const int tid = threadIdx.x;
    const int tx = tid & 15, ty = tid >> 4, ty8 = ty * 8;

    const float* A = g_agg + (size_t)r * (NN * FF);
    const float* bias = b1g + r * FF;

    load_w_paired(Wsp, (const float4*)(W1g + r * (FF * FF)), tid);
#pragma unroll
    for (int it = 0; it < 16; ++it) {
        int q = it * 256 + tid;
        int row = q >> 5, c4 = q & 31;
        float4 v = make_float4(0.f, 0.f, 0.f, 0.f);
        int grow = row0 + row;
        if (grow < NN) v = ((const float4*)A)[(size_t)grow * 32 + c4];
        float4* d = (float4*)Asd + row * 64 + c4 * 2;
        d[0] = make_float4(v.x, v.x, v.y, v.y);
        d[1] = make_float4(v.z, v.z, v.w, v.w);
    }
    __syncthreads();

    ull acc[8][4];
#pragma unroll
    for (int i = 0; i < 8; ++i)
#pragma unroll
        for (int jj = 0; jj < 4; ++jj)
            acc[i][jj] = pack2(bias[tx + 32 * jj], bias[tx + 32 * jj + 16]);

    const ull* Ap = (const ull*)Asd + ty8 * 128;
    const ull* Wp = (const ull*)Wsp;
#pragma unroll 8
    for (int k = 0; k < FF; ++k) {
        ull b2[4];
#pragma unroll
        for (int jj = 0; jj < 4; ++jj) b2[jj] = Wp[k * 64 + jj * 16 + tx];
#pragma unroll
        for (int i = 0; i < 8; ++i) {
            ull a2 = Ap[i * 128 + k];
#pragma unroll
            for (int jj = 0; jj < 4; ++jj) dfma(acc[i][jj], a2, b2[jj]);
        }
    }

    float* H = g_h + (size_t)r * (NN * FF);
#pragma unroll
    for (int i = 0; i < 8; ++i) {
        int grow = row0 + ty8 + i;
        if (grow < NN) {
#pragma unroll
            for (int jj = 0; jj < 4; ++jj) {
                float lo, hi;
                unpack2(acc[i][jj], lo, hi);
                H[(size_t)grow * FF + tx + 32 * jj] = lo;
                H[(size_t)grow * FF + tx + 32 * jj + 16] = hi;
            }
        }
    }

    // ---- fused BN stats: column sums of this tile ----
    __syncthreads();
    sh[tid] = 0.f;
    __syncthreads();
#pragma unroll
    for (int jj = 0; jj < 4; ++jj) {
        float slo = 0.f, qlo = 0.f, shi = 0.f, qhi = 0.f;
#pragma unroll
        for (int i = 0; i < 8; ++i) {
            if (row0 + ty8 + i < NN) {
                float lo, hi;
                unpack2(acc[i][jj], lo, hi);
                slo += lo; qlo = fmaf(lo, lo, qlo);
                shi += hi; qhi = fmaf(hi, hi, qhi);
            }
        }
        atomicAdd(&sh[tx + 32 * jj], slo);
        atomicAdd(&sh[128 + tx + 32 * jj], qlo);
        atomicAdd(&sh[tx + 32 * jj + 16], shi);
        atomicAdd(&sh[128 + tx + 32 * jj + 16], qhi);
    }
    __syncthreads();
    if (tid < 128) {
        atomicAdd(&g_sum[r * FF + tid], sh[tid]);
        atomicAdd(&g_sumsq[r * FF + tid], sh[128 + tid]);
    }
}

// ---------------- finalize BN: scale/shift per (r, channel) ---------------------
__global__ void finalize_kernel(const float* __restrict__ gamma,
                                const float* __restrict__ beta) {
    int i = threadIdx.x + blockIdx.x * blockDim.x;
    if (i < RR * FF) {
        float inv_n = 1.0f / (float)NN;
        float mean = g_sum[i] * inv_n;
        float var = g_sumsq[i] * inv_n - mean * mean;
        if (var < 0.f) var = 0.f;
        float sc = gamma[i] * rsqrtf(var + 1e-5f);
        g_scale[i] = sc;
        g_shift[i] = beta[i] - mean * sc;
    }
}

// ---------------- GEMM2 fused: out = x@W_self + b_self + sum_r b2[r]
//                  + sum_r relu(bn(h_r)) @ W2[r] --------------------------------
__global__ __launch_bounds__(256) void gemm2_kernel(const float* __restrict__ x,
                                                    const float* __restrict__ Wself,
                                                    const float* __restrict__ bself,
                                                    const float* __restrict__ W2g,
                                                    const float* __restrict__ b2g,
                                                    float* __restrict__ out) {
    extern __shared__ float sh[];
    float* Asd = sh;
    float* Wsp = sh + 32768;
    const int row0 = blockIdx.x * 128;
    const int tid = threadIdx.x;
    const int tx = tid & 15, ty = tid >> 4, ty8 = ty * 8;

    ull acc[8][4];
#pragma unroll
    for (int i = 0; i < 8; ++i)
#pragma unroll
        for (int jj = 0; jj < 4; ++jj) {
            int c0 = tx + 32 * jj, c1 = c0 + 16;
            float blo = bself[c0], bhi = bself[c1];
#pragma unroll
            for (int rr = 0; rr < RR; ++rr) {
                blo += b2g[rr * FF + c0];
                bhi += b2g[rr * FF + c1];
            }
            acc[i][jj] = pack2(blo, bhi);
        }

    for (int rel = 0; rel < 5; ++rel) {
        const float* A = (rel == 0) ? x : (g_h + (size_t)(rel - 1) * (NN * FF));
        const float* W = (rel == 0) ? Wself : (W2g + (rel - 1) * (FF * FF));
        const float* sc = g_scale + (rel - 1) * FF;
        const float* sf = g_shift + (rel - 1) * FF;

        __syncthreads();
        load_w_paired(Wsp, (const float4*)W, tid);
#pragma unroll
        for (int it = 0; it < 16; ++it) {
            int q = it * 256 + tid;
            int row = q >> 5, c4 = q & 31;
            float4 v = make_float4(0.f, 0.f, 0.f, 0.f);
            int grow = row0 + row;
            if (grow < NN) v = ((const float4*)A)[(size_t)grow * 32 + c4];
            if (rel > 0) {
                int kb = c4 * 4;
                v.x = fmaxf(fmaf(v.x, sc[kb + 0], sf[kb + 0]), 0.f);
                v.y = fmaxf(fmaf(v.y, sc[kb + 1], sf[kb + 1]), 0.f);
                v.z = fmaxf(fmaf(v.z, sc[kb + 2], sf[kb + 2]), 0.f);
                v.w = fmaxf(fmaf(v.w, sc[kb + 3], sf[kb + 3]), 0.f);
            }
            float4* d = (float4*)Asd + row * 64 + c4 * 2;
            d[0] = make_float4(v.x, v.x, v.y, v.y);
            d[1] = make_float4(v.z, v.z, v.w, v.w);
        }
        __syncthreads();

        const ull* Ap = (const ull*)Asd + ty8 * 128;
        const ull* Wp = (const ull*)Wsp;
#pragma unroll 8
        for (int k = 0; k < FF; ++k) {
            ull b2[4];
#pragma unroll
            for (int jj = 0; jj < 4; ++jj) b2[jj] = Wp[k * 64 + jj * 16 + tx];
#pragma unroll
            for (int i = 0; i < 8; ++i) {
                ull a2 = Ap[i * 128 + k];
#pragma unroll
                for (int jj = 0; jj < 4; ++jj) dfma(acc[i][jj], a2, b2[jj]);
            }
        }
    }

#pragma unroll
    for (int i = 0; i < 8; ++i) {
        int grow = row0 + ty8 + i;
        if (grow < NN) {
#pragma unroll
            for (int jj = 0; jj < 4; ++jj) {
                float lo, hi;
                unpack2(acc[i][jj], lo, hi);
                out[(size_t)grow * FF + tx + 32 * jj] = lo;
                out[(size_t)grow * FF + tx + 32 * jj + 16] = hi;
            }
        }
    }
}

// ---------------- launch ---------------------------------------------------------
extern "C" void kernel_launch(void* const* d_in, const int* in_sizes, int n_in,
                              void* d_out, int out_size) {
    const float* x     = (const float*)d_in[0];
    const int*   ei    = (const int*)d_in[1];
    const int*   et    = (const int*)d_in[2];
    const float* Wself = (const float*)d_in[3];
    const float* bself = (const float*)d_in[4];
    const float* W1    = (const float*)d_in[5];
    const float* b1    = (const float*)d_in[6];
    const float* gamma = (const float*)d_in[7];
    const float* beta  = (const float*)d_in[8];
    const float* W2    = (const float*)d_in[9];
    const float* b2    = (const float*)d_in[10];
    float* out = (float*)d_out;

    void* p_cnt = nullptr;
    cudaGetSymbolAddress(&p_cnt, g_cnt);
    cudaMemsetAsync(p_cnt, 0, RN * sizeof(int));

    const int SMEM = 49152 * 4;  // 192 KB dynamic shared
    cudaFuncSetAttribute(gemm1_kernel, cudaFuncAttributeMaxDynamicSharedMemorySize, SMEM);
    cudaFuncSetAttribute(gemm2_kernel, cudaFuncAttributeMaxDynamicSharedMemorySize, SMEM);

    hist_kernel<<<(EE + 255) / 256, 256>>>(ei, et);
    scan1_kernel<<<NBLK, 512>>>();
    scan2_kernel<<<1, 256>>>();
    reorder_kernel<<<(EE + 255) / 256, 256>>>(ei, et);
    segsum_kernel<<<(RN * 32 + 255) / 256, 256>>>((const float4*)x);
    gemm1_kernel<<<dim3((NN + 127) / 128, RR), 256, SMEM>>>(W1, b1);
    finalize_kernel<<<2, 256>>>(gamma, beta);
    gemm2_kernel<<<(NN + 127) / 128, 256, SMEM>>>(x, Wself, bself, W2, b2, out);
}

// round 6
// speedup vs baseline: 1.5599x; 1.5599x over previous
#include <cuda_runtime.h>
#include <cstdint>

#define NN 50000
#define EE 600000
#define FF 128
#define RR 4
#define RN (RR * NN)               // 200000 segments
#define NBLK ((RN + 1023) / 1024)  // 196 scan blocks

// ---------------- scratch (static device globals; no allocation) ----------------
__device__ __align__(16) float g_agg[(size_t)RR * NN * FF];
__device__ __align__(16) float g_h[(size_t)RR * NN * FF];
__device__ float g_sum[RR * FF];
__device__ float g_sumsq[RR * FF];
__device__ float g_scale[RR * FF];
__device__ float g_shift[RR * FF];
__device__ float g_bias2[FF];
__device__ int g_cnt[RN];
__device__ int g_off[RN];
__device__ int g_bsum[256];
__device__ int g_bscan[256];
__device__ int g_cur[RN];
__device__ int g_srcbuf[EE];
// 9 weight matrices (W1 r0..3, Wself, W2 r0..3), each as {hi 8192 u32, lo 8192 u32}
// transposed to [n][k] bf16-pair layout with XOR swizzle (matches smem layout).
__device__ __align__(16) unsigned g_wb[9u * 16384u];

// ---------------- helpers ---------------------------------------------------------
// split fp32 pair (a0=even k, a1=odd k) into bf16 hi-pair / lo-pair u32s.
// u32 layout: low 16 bits = element0 (even k), high 16 = element1 (odd k).
__device__ __forceinline__ void split2(float a0, float a1, unsigned& hi, unsigned& lo) {
    asm("cvt.rn.bf16x2.f32 %0, %1, %2;" : "=r"(hi) : "f"(a1), "f"(a0));
    float h0 = __uint_as_float(hi << 16);
    float h1 = __uint_as_float(hi & 0xffff0000u);
    float l0 = a0 - h0, l1 = a1 - h1;
    asm("cvt.rn.bf16x2.f32 %0, %1, %2;" : "=r"(lo) : "f"(l1), "f"(l0));
}

#define MMA_BF16(c, a, b)                                                          \
    asm volatile(                                                                  \
        "mma.sync.aligned.m16n8k16.row.col.f32.bf16.bf16.f32 "                     \
        "{%0,%1,%2,%3}, {%4,%5,%6,%7}, {%8,%9}, {%0,%1,%2,%3};"                    \
        : "+f"((c)[0]), "+f"((c)[1]), "+f"((c)[2]), "+f"((c)[3])                   \
        : "r"((a)[0]), "r"((a)[1]), "r"((a)[2]), "r"((a)[3]), "r"((b)[0]),         \
          "r"((b)[1]))

// ---------------- graph pipeline (validated) --------------------------------------
__global__ void hist_kernel(const int* __restrict__ ei, const int* __restrict__ et) {
    int e = blockIdx.x * blockDim.x + threadIdx.x;
    if (blockIdx.x == 0) {
        for (int i = threadIdx.x; i < RR * FF; i += blockDim.x) {
            g_sum[i] = 0.f;
            g_sumsq[i] = 0.f;
        }
    }
    if (e < EE) {
        int s = et[e] * NN + ei[e];
        atomicAdd(&g_cnt[s], 1);
    }
}

__global__ void scan1_kernel() {
    __shared__ int sh[512];
    int t = threadIdx.x;
    int base = blockIdx.x * 1024;
    int i0 = base + 2 * t, i1 = i0 + 1;
    int c0 = (i0 < RN) ? g_cnt[i0] : 0;
    int c1 = (i1 < RN) ? g_cnt[i1] : 0;
    if (i0 < RN) g_cur[i0] = 0;
    if (i1 < RN) g_cur[i1] = 0;
    int s = c0 + c1;
    sh[t] = s;
    __syncthreads();
    for (int d = 1; d < 512; d <<= 1) {
        int v = (t >= d) ? sh[t - d] : 0;
        __syncthreads();
        sh[t] += v;
        __syncthreads();
    }
    int excl = sh[t] - s;
    if (i0 < RN) g_off[i0] = excl;
    if (i1 < RN) g_off[i1] = excl + c0;
    if (t == 511) g_bsum[blockIdx.x] = sh[511];
}

__global__ void scan2_kernel() {
    __shared__ int sh[256];
    int t = threadIdx.x;
    int v = (t < NBLK) ? g_bsum[t] : 0;
    sh[t] = v;
    __syncthreads();
    for (int d = 1; d < 256; d <<= 1) {
        int u = (t >= d) ? sh[t - d] : 0;
        __syncthreads();
        sh[t] += u;
        __syncthreads();
    }
    g_bscan[t] = sh[t] - v;
}

__global__ void reorder_kernel(const int* __restrict__ ei, const int* __restrict__ et) {
    int e = blockIdx.x * blockDim.x + threadIdx.x;
    if (e >= EE) return;
    int s = et[e] * NN + ei[e];
    int base = g_off[s] + g_bscan[s >> 10];
    int pos = base + atomicAdd(&g_cur[s], 1);
    g_srcbuf[pos] = ei[EE + e];
}

__global__ void segsum_kernel(const float4* __restrict__ x4) {
    int warp = (blockIdx.x * blockDim.x + threadIdx.x) >> 5;
    int lane = threadIdx.x & 31;
    if (warp >= RN) return;
    int row = warp % NN;
    int start = g_off[warp] + g_bscan[warp >> 10];
    int cnt = g_cnt[warp];
    float4 acc = x4[(size_t)row * 32 + lane];
    for (int i = 0; i < cnt; ++i) {
        int src = g_srcbuf[start + i];
        float4 v = x4[(size_t)src * 32 + lane];
        acc.x += v.x; acc.y += v.y; acc.z += v.z; acc.w += v.w;
    }
    ((float4*)g_agg)[(size_t)warp * 32 + lane] = acc;
}

// ---------------- weight prep: transpose + bf16 split + swizzle -------------------
__global__ void prep_w_kernel(const float* __restrict__ W1, const float* __restrict__ Wself,
                              const float* __restrict__ W2) {
    int m = blockIdx.x;  // 0..8
    const float* W = (m < 4) ? (W1 + m * (FF * FF))
                             : ((m == 4) ? Wself : (W2 + (m - 5) * (FF * FF)));
    unsigned* outh = g_wb + (size_t)m * 16384u;
    unsigned* outl = outh + 8192;
    for (int q = threadIdx.x; q < 8192; q += blockDim.x) {
        int n = q & 127, ku = q >> 7;  // ku = k-pair index 0..63
        float a0 = W[(2 * ku) * FF + n];       // B[n][2ku]   = W[2ku][n]
        float a1 = W[(2 * ku + 1) * FF + n];
        unsigned hi, lo;
        split2(a0, a1, hi, lo);
        unsigned idx = n * 64 + (ku ^ ((n & 7) << 2));
        outh[idx] = hi;
        outl[idx] = lo;
    }
}

// ---------------- HMMA gemm machinery ---------------------------------------------
// smem (u32 units): Ah[0,8192) Al[8192,16384) Bh[16384,24576) Bl[24576,32768)
// layout: buf[row*64 + (ku ^ ((row&7)<<2))], row=M-row (A) or N-col (B), ku=k/2.
#define SMEM_BYTES 131072

struct Frag {
    unsigned ah[4][4], al[4][4], bh[4][2], bl[4][2];
};

__device__ __forceinline__ void load_frags(Frag& f, const unsigned* Ah, const unsigned* Al,
                                           const unsigned* Bh, const unsigned* Bl, int wm,
                                           int wn, int gq, int tq, int ku0) {
#pragma unroll
    for (int mi = 0; mi < 4; ++mi) {
        int row = wm + mi * 16 + gq;
        int sw = (row & 7) << 2;
        int i0 = row * 64 + ((ku0 + tq) ^ sw);
        int i1 = (row + 8) * 64 + ((ku0 + tq) ^ sw);
        int i2 = row * 64 + ((ku0 + 4 + tq) ^ sw);
        int i3 = (row + 8) * 64 + ((ku0 + 4 + tq) ^ sw);
        f.ah[mi][0] = Ah[i0]; f.ah[mi][1] = Ah[i1];
        f.ah[mi][2] = Ah[i2]; f.ah[mi][3] = Ah[i3];
        f.al[mi][0] = Al[i0]; f.al[mi][1] = Al[i1];
        f.al[mi][2] = Al[i2]; f.al[mi][3] = Al[i3];
    }
#pragma unroll
    for (int nj = 0; nj < 4; ++nj) {
        int nb = wn + nj * 8 + gq;
        int sw = (nb & 7) << 2;
        int i0 = nb * 64 + ((ku0 + tq) ^ sw);
        int i1 = nb * 64 + ((ku0 + 4 + tq) ^ sw);
        f.bh[nj][0] = Bh[i0]; f.bh[nj][1] = Bh[i1];
        f.bl[nj][0] = Bl[i0]; f.bl[nj][1] = Bl[i1];
    }
}

__device__ __forceinline__ void mma_all(float (*acc)[4][4], const Frag& f) {
#pragma unroll
    for (int mi = 0; mi < 4; ++mi)
#pragma unroll
        for (int nj = 0; nj < 4; ++nj) {
            MMA_BF16(acc[mi][nj], f.ah[mi], f.bh[nj]);
            MMA_BF16(acc[mi][nj], f.ah[mi], f.bl[nj]);
            MMA_BF16(acc[mi][nj], f.al[mi], f.bh[nj]);
        }
}

__device__ __forceinline__ void copy_b(unsigned* Bh, int mat, int tid) {
    const float4* src = (const float4*)(g_wb + (size_t)mat * 16384u);
    float4* dst = (float4*)Bh;  // Bh..Bl contiguous: 16384 u32 = 4096 float4
#pragma unroll
    for (int it = 0; it < 16; ++it) dst[it * 256 + tid] = src[it * 256 + tid];
}

// ---------------- GEMM1: g_h[r] = g_agg[r] @ W1[r] + b1[r] -------------------------
__global__ __launch_bounds__(256, 1) void gemm1_tc(const float* __restrict__ b1g) {
    extern __shared__ unsigned sm[];
    unsigned* Ah = sm;
    unsigned* Al = sm + 8192;
    unsigned* Bh = sm + 16384;
    unsigned* Bl = sm + 24576;
    const int tid = threadIdx.x, wid = tid >> 5, lane = tid & 31;
    const int gq = lane >> 2, tq = lane & 3;
    const int wm = (wid & 1) * 64, wn = (wid >> 1) * 32;
    const int r = blockIdx.y, row0 = blockIdx.x * 128;

    copy_b(Bh, r, tid);

    const float* A = g_agg + (size_t)r * (NN * FF);
#pragma unroll
    for (int it = 0; it < 16; ++it) {
        int q = it * 256 + tid;
        int row = q >> 5, c4 = q & 31;
        float4 v = make_float4(0.f, 0.f, 0.f, 0.f);
        int grow = row0 + row;
        if (grow < NN) v = ((const float4*)A)[(size_t)grow * 32 + c4];
        unsigned h0, l0, h1, l1;
        split2(v.x, v.y, h0, l0);
        split2(v.z, v.w, h1, l1);
        int idx = row * 64 + ((c4 * 2) ^ ((row & 7) << 2));
        Ah[idx] = h0; Ah[idx + 1] = h1;
        Al[idx] = l0; Al[idx + 1] = l1;
    }
    __syncthreads();

    float acc[4][4][4];
#pragma unroll
    for (int mi = 0; mi < 4; ++mi)
#pragma unroll
        for (int nj = 0; nj < 4; ++nj)
#pragma unroll
            for (int c = 0; c < 4; ++c) acc[mi][nj][c] = 0.f;

#pragma unroll
    for (int kc = 0; kc < 8; ++kc) {
        Frag f;
        load_frags(f, Ah, Al, Bh, Bl, wm, wn, gq, tq, kc * 8);
        mma_all(acc, f);
    }

    const float* bias = b1g + r * FF;
    float* H = g_h + (size_t)r * (NN * FF);
#pragma unroll
    for (int mi = 0; mi < 4; ++mi) {
        int ra = row0 + wm + mi * 16 + gq;
#pragma unroll
        for (int nj = 0; nj < 4; ++nj) {
            int col = wn + nj * 8 + 2 * tq;
            float bx = bias[col], by = bias[col + 1];
            if (ra < NN)
                *(float2*)(H + (size_t)ra * FF + col) =
                    make_float2(acc[mi][nj][0] + bx, acc[mi][nj][1] + by);
            if (ra + 8 < NN)
                *(float2*)(H + (size_t)(ra + 8) * FF + col) =
                    make_float2(acc[mi][nj][2] + bx, acc[mi][nj][3] + by);
        }
    }
}

// ---------------- BN stats over g_h (vectorized) -----------------------------------
#define SROWS 1024
__global__ void stats_kernel() {
    int r = blockIdx.y;
    int tid = threadIdx.x;
    int c4 = tid & 31;
    int rg = tid >> 5;
    const float4* H4 = (const float4*)(g_h + (size_t)r * (NN * FF));
    int row = blockIdx.x * SROWS + rg;
    int rend = blockIdx.x * SROWS + SROWS;
    if (rend > NN) rend = NN;
    float4 s = make_float4(0.f, 0.f, 0.f, 0.f);
    float4 q = make_float4(0.f, 0.f, 0.f, 0.f);
    for (; row < rend; row += 8) {
        float4 v = H4[(size_t)row * 32 + c4];
        s.x += v.x; s.y += v.y; s.z += v.z; s.w += v.w;
        q.x = fmaf(v.x, v.x, q.x); q.y = fmaf(v.y, v.y, q.y);
        q.z = fmaf(v.z, v.z, q.z); q.w = fmaf(v.w, v.w, q.w);
    }
    __shared__ float shs[1024], shq[1024];
    int bb = rg * 128 + c4 * 4;
    shs[bb + 0] = s.x; shs[bb + 1] = s.y; shs[bb + 2] = s.z; shs[bb + 3] = s.w;
    shq[bb + 0] = q.x; shq[bb + 1] = q.y; shq[bb + 2] = q.z; shq[bb + 3] = q.w;
    __syncthreads();
    if (tid < 128) {
        float a = 0.f, b = 0.f;
#pragma unroll
        for (int g = 0; g < 8; ++g) {
            a += shs[g * 128 + tid];
            b += shq[g * 128 + tid];
        }
        atomicAdd(&g_sum[r * FF + tid], a);
        atomicAdd(&g_sumsq[r * FF + tid], b);
    }
}

// ---------------- finalize BN + combined bias ---------------------------------------
__global__ void finalize_kernel(const float* __restrict__ gamma, const float* __restrict__ beta,
                                const float* __restrict__ bself, const float* __restrict__ b2g) {
    int i = threadIdx.x + blockIdx.x * blockDim.x;
    if (i < RR * FF) {
        float inv_n = 1.0f / (float)NN;
        float mean = g_sum[i] * inv_n;
        float var = g_sumsq[i] * inv_n - mean * mean;
        if (var < 0.f) var = 0.f;
        float sc = gamma[i] * rsqrtf(var + 1e-5f);
        g_scale[i] = sc;
        g_shift[i] = beta[i] - mean * sc;
    }
    if (i < FF) {
        float b = bself[i];
#pragma unroll
        for (int rr = 0; rr < RR; ++rr) b += b2g[rr * FF + i];
        g_bias2[i] = b;
    }
}

// ---------------- GEMM2: out = x@Wself + sum_r relu(bn(h_r))@W2[r] + bias ----------
__global__ __launch_bounds__(256, 1) void gemm2_tc(const float* __restrict__ x,
                                                   float* __restrict__ out) {
    extern __shared__ unsigned sm[];
    unsigned* Ah = sm;
    unsigned* Al = sm + 8192;
    unsigned* Bh = sm + 16384;
    unsigned* Bl = sm + 24576;
    const int tid = threadIdx.x, wid = tid >> 5, lane = tid & 31;
    const int gq = lane >> 2, tq = lane & 3;
    const int wm = (wid & 1) * 64, wn = (wid >> 1) * 32;
    const int row0 = blockIdx.x * 128;

    float acc[4][4][4];
#pragma unroll
    for (int mi = 0; mi < 4; ++mi)
#pragma unroll
        for (int nj = 0; nj < 4; ++nj)
#pragma unroll
            for (int c = 0; c < 4; ++c) acc[mi][nj][c] = 0.f;

    for (int rel = 0; rel < 5; ++rel) {
        __syncthreads();  // previous compute done reading smem
        copy_b(Bh, 4 + rel, tid);

        const float* A = (rel == 0) ? x : (g_h + (size_t)(rel - 1) * (NN * FF));
        const float* sc = g_scale + (rel - 1) * FF;
        const float* sf = g_shift + (rel - 1) * FF;
#pragma unroll
        for (int it = 0; it < 16; ++it) {
            int q = it * 256 + tid;
            int row = q >> 5, c4 = q & 31, k4 = c4 * 4;
            float4 v = make_float4(0.f, 0.f, 0.f, 0.f);
            int grow = row0 + row;
            if (grow < NN) {
                v = ((const float4*)A)[(size_t)grow * 32 + c4];
                if (rel > 0) {
                    v.x = fmaxf(fmaf(v.x, sc[k4 + 0], sf[k4 + 0]), 0.f);
                    v.y = fmaxf(fmaf(v.y, sc[k4 + 1], sf[k4 + 1]), 0.f);
                    v.z = fmaxf(fmaf(v.z, sc[k4 + 2], sf[k4 + 2]), 0.f);
                    v.w = fmaxf(fmaf(v.w, sc[k4 + 3], sf[k4 + 3]), 0.f);
                }
            }
            unsigned h0, l0, h1, l1;
            split2(v.x, v.y, h0, l0);
            split2(v.z, v.w, h1, l1);
            int idx = row * 64 + ((c4 * 2) ^ ((row & 7) << 2));
            Ah[idx] = h0; Ah[idx + 1] = h1;
            Al[idx] = l0; Al[idx + 1] = l1;
        }
        __syncthreads();

#pragma unroll
        for (int kc = 0; kc < 8; ++kc) {
            Frag f;
            load_frags(f, Ah, Al, Bh, Bl, wm, wn, gq, tq, kc * 8);
            mma_all(acc, f);
        }
    }

#pragma unroll
    for (int mi = 0; mi < 4; ++mi) {
        int ra = row0 + wm + mi * 16 + gq;
#pragma unroll
        for (int nj = 0; nj < 4; ++nj) {
            int col = wn + nj * 8 + 2 * tq;
            float bx = g_bias2[col], by = g_bias2[col + 1];
            if (ra < NN)
                *(float2*)(out + (size_t)ra * FF + col) =
                    make_float2(acc[mi][nj][0] + bx, acc[mi][nj][1] + by);
            if (ra + 8 < NN)
                *(float2*)(out + (size_t)(ra + 8) * FF + col) =
                    make_float2(acc[mi][nj][2] + bx, acc[mi][nj][3] + by);
        }
    }
}

// ---------------- launch ---------------------------------------------------------
extern "C" void kernel_launch(void* const* d_in, const int* in_sizes, int n_in,
                              void* d_out, int out_size) {
    const float* x     = (const float*)d_in[0];
    const int*   ei    = (const int*)d_in[1];
    const int*   et    = (const int*)d_in[2];
    const float* Wself = (const float*)d_in[3];
    const float* bself = (const float*)d_in[4];
    const float* W1    = (const float*)d_in[5];
    const float* b1    = (const float*)d_in[6];
    const float* gamma = (const float*)d_in[7];
    const float* beta  = (const float*)d_in[8];
    const float* W2    = (const float*)d_in[9];
    const float* b2    = (const float*)d_in[10];
    float* out = (float*)d_out;

    void* p_cnt = nullptr;
    cudaGetSymbolAddress(&p_cnt, g_cnt);
    cudaMemsetAsync(p_cnt, 0, RN * sizeof(int));

    cudaFuncSetAttribute(gemm1_tc, cudaFuncAttributeMaxDynamicSharedMemorySize, SMEM_BYTES);
    cudaFuncSetAttribute(gemm2_tc, cudaFuncAttributeMaxDynamicSharedMemorySize, SMEM_BYTES);

    const int G1 = (NN + 127) / 128;  // 391

    prep_w_kernel<<<9, 256>>>(W1, Wself, W2);
    hist_kernel<<<(EE + 255) / 256, 256>>>(ei, et);
    scan1_kernel<<<NBLK, 512>>>();
    scan2_kernel<<<1, 256>>>();
    reorder_kernel<<<(EE + 255) / 256, 256>>>(ei, et);
    segsum_kernel<<<(RN * 32 + 255) / 256, 256>>>((const float4*)x);
    gemm1_tc<<<dim3(G1, RR), 256, SMEM_BYTES>>>(b1);
    stats_kernel<<<dim3((NN + SROWS - 1) / SROWS, RR), 256>>>();
    finalize_kernel<<<2, 256>>>(gamma, beta, bself, b2);
    gemm2_tc<<<G1, 256, SMEM_BYTES>>>(x, out);
}